// round 12
// baseline (speedup 1.0000x reference)
#include <cuda_runtime.h>
#include <cuda_fp16.h>
#include <cstdint>

// ============================================================================
// GhostLinear: out[M,N] = X[M,K] @ W^T,  W[N,K] = lut[indices]*scale
// M=16384, N=4096, K=4096
// Toolchain: PTX target sm_103 (no 'a') -> no tcgen05.ld -> legacy mma.sync
// (HMMA rt~8/SMSP => GEMM floor ~0.96ms).
// R10: 1202us, tensor=80.1% (persistent CTAs, cross-tile pipeline splice).
// R11: decouple the ks7 pileup -> CP_WAIT+bar moved to ks5 (still 2 MMA
// bursts after the ks3 commit), ks7 keeps only the cross-kit LDSM which
// overlaps its own MMA burst. Unroll kit loop by 2 for constant stage parity.
// ============================================================================

#define M_TOTAL 16384
#define N_TOTAL 4096
#define K_TOTAL 4096
#define CODES   256

#define BM 128
#define BN 256
#define BK 128
#define NITER (K_TOTAL / BK)             // 32 kits
#define KS_PER_KIT 8                      // eight k16 steps per kit

#define NTILES ((M_TOTAL / BM) * (N_TOTAL / BN))   // 128 * 16 = 2048
#define GRID 148

#define BKP 136                           // padded halves per smem row (272 B)
#define A_STAGE_HALFS (BM * BKP)          // 17408
#define B_STAGE_HALFS (BN * BKP)          // 34816
#define STAGE_HALFS (A_STAGE_HALFS + B_STAGE_HALFS)      // 52224
#define SMEM_BYTES (2 * STAGE_HALFS * 2)                 // 208896

__device__ __align__(1024) __half g_X[(size_t)M_TOTAL * K_TOTAL];  // 128 MB
__device__ __align__(1024) __half g_W[(size_t)N_TOTAL * K_TOTAL];  //  32 MB

__device__ __forceinline__ uint32_t smem_u32(const void* p) {
    uint32_t a;
    asm("{ .reg .u64 t; cvta.to.shared.u64 t, %1; cvt.u32.u64 %0, t; }"
        : "=r"(a) : "l"(p));
    return a;
}

#define CP_ASYNC16(dst32, src) \
    asm volatile("cp.async.cg.shared.global [%0], [%1], 16;" \
                 :: "r"(dst32), "l"(src) : "memory")
#define CP_COMMIT() asm volatile("cp.async.commit_group;" ::: "memory")
#define CP_WAIT(n)  asm volatile("cp.async.wait_group %0;" :: "n"(n) : "memory")

#define LDSM4(r0, r1, r2, r3, addr) \
    asm volatile("ldmatrix.sync.aligned.m8n8.x4.shared.b16 {%0,%1,%2,%3}, [%4];" \
                 : "=r"(r0), "=r"(r1), "=r"(r2), "=r"(r3) : "r"(addr))

#define STG_CS_F2(ptr, v0, v1) \
    asm volatile("st.global.cs.v2.f32 [%0], {%1, %2};" \
                 :: "l"(ptr), "f"(v0), "f"(v1) : "memory")

__device__ __forceinline__ void mma16816(float* c, const uint32_t* a, const uint32_t* b) {
    asm volatile(
        "mma.sync.aligned.m16n8k16.row.col.f32.f16.f16.f32 "
        "{%0,%1,%2,%3}, {%4,%5,%6,%7}, {%8,%9}, {%0,%1,%2,%3};"
        : "+f"(c[0]), "+f"(c[1]), "+f"(c[2]), "+f"(c[3])
        : "r"(a[0]), "r"(a[1]), "r"(a[2]), "r"(a[3]), "r"(b[0]), "r"(b[1]));
}

// ---------------------------------------------------------------------------
// Fused converter: blocks [0, XB) convert X fp32->fp16 (8/thread),
// blocks [XB, XB+WB) dequant W via codebook (4/thread).
// ---------------------------------------------------------------------------
#define XBLOCKS 32768
#define WBLOCKS 16384

__device__ __forceinline__ uint32_t h2u(__half2 h) {
    return *reinterpret_cast<uint32_t*>(&h);
}

__global__ void __launch_bounds__(256) convert_kernel(const float* __restrict__ x,
                                                      const int* __restrict__ idx,
                                                      const float* __restrict__ scale,
                                                      const float* __restrict__ lut) {
    if (blockIdx.x < XBLOCKS) {
        size_t i = ((size_t)blockIdx.x * 256 + threadIdx.x) * 8;
        float4 a = *reinterpret_cast<const float4*>(x + i);
        float4 b = *reinterpret_cast<const float4*>(x + i + 4);
        uint4 o;
        o.x = h2u(__floats2half2_rn(a.x, a.y));
        o.y = h2u(__floats2half2_rn(a.z, a.w));
        o.z = h2u(__floats2half2_rn(b.x, b.y));
        o.w = h2u(__floats2half2_rn(b.z, b.w));
        *reinterpret_cast<uint4*>(g_X + i) = o;
    } else {
        __shared__ float slut[CODES];
        if (threadIdx.x < CODES) slut[threadIdx.x] = lut[threadIdx.x];
        __syncthreads();
        size_t i = ((size_t)(blockIdx.x - XBLOCKS) * 256 + threadIdx.x) * 4;
        int4 v = *reinterpret_cast<const int4*>(idx + i);
        float s = scale[i >> 12];   // K_TOTAL elements per output row
        uint2 o;
        o.x = h2u(__floats2half2_rn(slut[v.x] * s, slut[v.y] * s));
        o.y = h2u(__floats2half2_rn(slut[v.z] * s, slut[v.w] * s));
        *reinterpret_cast<uint2*>(g_W + i) = o;
    }
}

// ---------------------------------------------------------------------------
// Persistent GEMM: 148 CTAs; each walks tiles bid, bid+148, ...
// CTA tile = 128(M) x 256(N); BK=128, 2 smem stages; 8 warps (2M x 4N),
// warp tile 64x64; fragment double-buffer pipelined across kit AND tile
// boundaries. Wait+barrier at ks5; only the cross-kit LDSM remains at ks7.
// ---------------------------------------------------------------------------
__global__ void __launch_bounds__(256, 1) gemm_kernel(const __half* __restrict__ X,
                                                      const __half* __restrict__ W,
                                                      float* __restrict__ out) {
    extern __shared__ __half sm[];
    const uint32_t smem_base = smem_u32(sm);
    const int tid  = threadIdx.x;
    const int lane = tid & 31;
    const int wid  = tid >> 5;
    const int warp_m = wid & 1;    // 64-row band
    const int warp_n = wid >> 1;   // 64-col band (0..3)

    // --- cp.async mapping: chunk q -> row = (tid>>4) + 16q, col = (tid&15)*8
    const int crow = tid >> 4, ccol = tid & 15;
    const size_t   offA  = (size_t)crow * K_TOTAL + ccol * 8;   // same for B
    const uint32_t dA    = (uint32_t)(crow * BKP + ccol * 8) * 2;
    const uint32_t dB    = (uint32_t)(A_STAGE_HALFS + crow * BKP + ccol * 8) * 2;
    const size_t   gstep = (size_t)16 * K_TOTAL;
    const uint32_t dstep = (uint32_t)(16 * BKP) * 2;

    // --- ldmatrix per-thread byte offsets within a stage ---
    const uint32_t a_off0 = (uint32_t)((warp_m * 64 + (lane & 15)) * BKP
                                       + (lane >> 4) * 8) * 2;
    const uint32_t b_off0 = (uint32_t)(A_STAGE_HALFS * 2)
        + (uint32_t)((warp_n * 64 + (lane & 7) + ((lane >> 4) & 1) * 8) * BKP
                     + ((lane >> 3) & 1) * 8) * 2;

    float acc[4][8][4];
    uint32_t a[2][4][4], b[2][8][2];

    #define LOAD_FRAGS(bf, sb, colk) do {                                      \
        const uint32_t _aB = (sb) + a_off0 + (uint32_t)((colk) * 16 * 2);      \
        const uint32_t _bB = (sb) + b_off0 + (uint32_t)((colk) * 16 * 2);      \
        _Pragma("unroll")                                                      \
        for (int _t = 0; _t < 4; _t++)                                         \
            LDSM4(a[bf][_t][0], a[bf][_t][1], a[bf][_t][2], a[bf][_t][3],      \
                  _aB + (uint32_t)(_t * 16 * BKP) * 2);                        \
        _Pragma("unroll")                                                      \
        for (int _jj = 0; _jj < 4; _jj++)                                      \
            LDSM4(b[bf][_jj * 2][0], b[bf][_jj * 2][1],                        \
                  b[bf][_jj * 2 + 1][0], b[bf][_jj * 2 + 1][1],                \
                  _bB + (uint32_t)(_jj * 16 * BKP) * 2);                       \
    } while (0)

    int tile = blockIdx.x;

    // --- prologue: fill stage 0 of the first tile ---
    {
        const int m_base = (tile >> 4) * BM;   // 16 n-tiles, n fastest
        const int n_base = (tile & 15) * BN;
        const __half* pA = X + (size_t)m_base * K_TOTAL + offA;
        const __half* pB = W + (size_t)n_base * K_TOTAL + offA;
        #pragma unroll
        for (int q = 0; q < 8; q++)  CP_ASYNC16(smem_base + dA + q * dstep, pA + q * gstep);
        #pragma unroll
        for (int q = 0; q < 16; q++) CP_ASYNC16(smem_base + dB + q * dstep, pB + q * gstep);
        CP_COMMIT();
    }
    CP_WAIT(0);
    __syncthreads();
    LOAD_FRAGS(0, smem_base, 0);

    // --- persistent tile loop ---
    while (true) {
        const int m_base = (tile >> 4) * BM;
        const int n_base = (tile & 15) * BN;
        const __half* gA = X + (size_t)m_base * K_TOTAL + offA;
        const __half* gB = W + (size_t)n_base * K_TOTAL + offA;

        const int  next_tile = tile + GRID;
        const bool has_next_tile = next_tile < NTILES;
        const __half* nA = has_next_tile
            ? X + (size_t)((next_tile >> 4) * BM) * K_TOTAL + offA : gA;
        const __half* nB = has_next_tile
            ? W + (size_t)((next_tile & 15) * BN) * K_TOTAL + offA : gB;

        #pragma unroll
        for (int t = 0; t < 4; t++)
            #pragma unroll
            for (int j = 0; j < 8; j++)
                #pragma unroll
                for (int e = 0; e < 4; e++) acc[t][j][e] = 0.f;

        #pragma unroll 2
        for (int kit = 0; kit < NITER; kit++) {
            const uint32_t sb  = smem_base + (uint32_t)((kit & 1) * STAGE_HALFS) * 2;
            const uint32_t sb2 = smem_base + (uint32_t)(((kit + 1) & 1) * STAGE_HALFS) * 2;
            const bool last_kit = (kit == NITER - 1);
            const __half* pA = last_kit ? nA : gA + (size_t)(kit + 1) * BK;
            const __half* pB = last_kit ? nB : gB + (size_t)(kit + 1) * BK;
            const bool do_pref = !last_kit || has_next_tile;

            #pragma unroll
            for (int ks = 0; ks < KS_PER_KIT; ks++) {
                const int cur = ks & 1, nxt = cur ^ 1;

                if (ks < 4 && do_pref) {   // 6 cp.async issues per step
                    #pragma unroll
                    for (int u = 0; u < 2; u++) {
                        int q = 2 * ks + u;
                        CP_ASYNC16(sb2 + dA + q * dstep, pA + q * gstep);
                    }
                    #pragma unroll
                    for (int u = 0; u < 4; u++) {
                        int q = 4 * ks + u;
                        CP_ASYNC16(sb2 + dB + q * dstep, pB + q * gstep);
                    }
                    if (ks == 3) CP_COMMIT();
                }

                // Decoupled: prove stage kit+1 resident at ks5 (2 MMA bursts
                // after the ks3 commit); the cross-kit LDSM at ks7 then has
                // no wait/barrier in front of it.
                if (ks == 5 && do_pref) {
                    CP_WAIT(0);
                    __syncthreads();
                }

                if (ks < KS_PER_KIT - 1) {
                    LOAD_FRAGS(nxt, sb, ks + 1);
                } else if (do_pref) {
                    LOAD_FRAGS(nxt, sb2, 0);
                }

                #pragma unroll
                for (int t = 0; t < 4; t++)
                    #pragma unroll
                    for (int j = 0; j < 8; j++)
                        mma16816(acc[t][j], a[cur][t], b[cur][j]);
            }
        }

        // --- epilogue (overlaps next tile's in-flight stage-0 copies) ---
        #pragma unroll
        for (int t = 0; t < 4; t++) {
            int row = m_base + warp_m * 64 + t * 16 + (lane >> 2);
            #pragma unroll
            for (int j = 0; j < 8; j++) {
                int col = n_base + warp_n * 64 + j * 8 + (lane & 3) * 2;
                float* p0 = out + (size_t)row * N_TOTAL + col;
                float* p1 = out + (size_t)(row + 8) * N_TOTAL + col;
                STG_CS_F2(p0, acc[t][j][0], acc[t][j][1]);
                STG_CS_F2(p1, acc[t][j][2], acc[t][j][3]);
            }
        }

        if (!has_next_tile) break;
        tile = next_tile;
    }
    #undef LOAD_FRAGS
}

// ---------------------------------------------------------------------------
// Host launcher
// ---------------------------------------------------------------------------
extern "C" void kernel_launch(void* const* d_in, const int* in_sizes, int n_in,
                              void* d_out, int out_size) {
    (void)in_sizes; (void)n_in; (void)out_size;
    const float* x     = (const float*)d_in[0];
    const float* scale = (const float*)d_in[1];
    const float* lut   = (const float*)d_in[2];
    const int*   idx   = (const int*)d_in[3];
    float* out = (float*)d_out;

    void *pX = nullptr, *pW = nullptr;
    cudaGetSymbolAddress(&pX, g_X);
    cudaGetSymbolAddress(&pW, g_W);

    cudaFuncSetAttribute(gemm_kernel, cudaFuncAttributeMaxDynamicSharedMemorySize,
                         SMEM_BYTES);

    convert_kernel<<<XBLOCKS + WBLOCKS, 256>>>(x, idx, scale, lut);

    gemm_kernel<<<GRID, 256, SMEM_BYTES>>>((const __half*)pX, (const __half*)pW, out);
}

// round 13
// speedup vs baseline: 1.4933x; 1.4933x over previous
#include <cuda_runtime.h>
#include <cuda_fp16.h>
#include <cstdint>

// ============================================================================
// GhostLinear: out[M,N] = X[M,K] @ W^T,  W[N,K] = lut[indices]*scale
// M=16384, N=4096, K=4096
// Toolchain: PTX target sm_103 (no 'a') -> no tcgen05.ld -> legacy mma.sync
// (HMMA rt~8/SMSP => GEMM floor ~0.96ms).
// R10: 1202us, tensor=80.1%. R11 (+unroll2, wait@ks5) regressed to 1767us:
// tensor-ACTIVE time grew 58% => HMMA rt inflated by RF bank conflicts from
// the unroll-2 register reallocation. R12 = R10 verbatim EXCEPT the wait+bar
// moves ks7 -> ks6 (3 MMA bursts of cover after the ks3 commit; ks7 is
// barrier-free). No unroll pragma.
// ============================================================================

#define M_TOTAL 16384
#define N_TOTAL 4096
#define K_TOTAL 4096
#define CODES   256

#define BM 128
#define BN 256
#define BK 128
#define NITER (K_TOTAL / BK)             // 32 kits
#define KS_PER_KIT 8                      // eight k16 steps per kit

#define NTILES ((M_TOTAL / BM) * (N_TOTAL / BN))   // 128 * 16 = 2048
#define GRID 148

#define BKP 136                           // padded halves per smem row (272 B)
#define A_STAGE_HALFS (BM * BKP)          // 17408
#define B_STAGE_HALFS (BN * BKP)          // 34816
#define STAGE_HALFS (A_STAGE_HALFS + B_STAGE_HALFS)      // 52224
#define SMEM_BYTES (2 * STAGE_HALFS * 2)                 // 208896

__device__ __align__(1024) __half g_X[(size_t)M_TOTAL * K_TOTAL];  // 128 MB
__device__ __align__(1024) __half g_W[(size_t)N_TOTAL * K_TOTAL];  //  32 MB

__device__ __forceinline__ uint32_t smem_u32(const void* p) {
    uint32_t a;
    asm("{ .reg .u64 t; cvta.to.shared.u64 t, %1; cvt.u32.u64 %0, t; }"
        : "=r"(a) : "l"(p));
    return a;
}

#define CP_ASYNC16(dst32, src) \
    asm volatile("cp.async.cg.shared.global [%0], [%1], 16;" \
                 :: "r"(dst32), "l"(src) : "memory")
#define CP_COMMIT() asm volatile("cp.async.commit_group;" ::: "memory")
#define CP_WAIT(n)  asm volatile("cp.async.wait_group %0;" :: "n"(n) : "memory")

#define LDSM4(r0, r1, r2, r3, addr) \
    asm volatile("ldmatrix.sync.aligned.m8n8.x4.shared.b16 {%0,%1,%2,%3}, [%4];" \
                 : "=r"(r0), "=r"(r1), "=r"(r2), "=r"(r3) : "r"(addr))

#define STG_CS_F2(ptr, v0, v1) \
    asm volatile("st.global.cs.v2.f32 [%0], {%1, %2};" \
                 :: "l"(ptr), "f"(v0), "f"(v1) : "memory")

__device__ __forceinline__ void mma16816(float* c, const uint32_t* a, const uint32_t* b) {
    asm volatile(
        "mma.sync.aligned.m16n8k16.row.col.f32.f16.f16.f32 "
        "{%0,%1,%2,%3}, {%4,%5,%6,%7}, {%8,%9}, {%0,%1,%2,%3};"
        : "+f"(c[0]), "+f"(c[1]), "+f"(c[2]), "+f"(c[3])
        : "r"(a[0]), "r"(a[1]), "r"(a[2]), "r"(a[3]), "r"(b[0]), "r"(b[1]));
}

// ---------------------------------------------------------------------------
// Fused converter: blocks [0, XB) convert X fp32->fp16 (8/thread),
// blocks [XB, XB+WB) dequant W via codebook (4/thread).
// ---------------------------------------------------------------------------
#define XBLOCKS 32768
#define WBLOCKS 16384

__device__ __forceinline__ uint32_t h2u(__half2 h) {
    return *reinterpret_cast<uint32_t*>(&h);
}

__global__ void __launch_bounds__(256) convert_kernel(const float* __restrict__ x,
                                                      const int* __restrict__ idx,
                                                      const float* __restrict__ scale,
                                                      const float* __restrict__ lut) {
    if (blockIdx.x < XBLOCKS) {
        size_t i = ((size_t)blockIdx.x * 256 + threadIdx.x) * 8;
        float4 a = *reinterpret_cast<const float4*>(x + i);
        float4 b = *reinterpret_cast<const float4*>(x + i + 4);
        uint4 o;
        o.x = h2u(__floats2half2_rn(a.x, a.y));
        o.y = h2u(__floats2half2_rn(a.z, a.w));
        o.z = h2u(__floats2half2_rn(b.x, b.y));
        o.w = h2u(__floats2half2_rn(b.z, b.w));
        *reinterpret_cast<uint4*>(g_X + i) = o;
    } else {
        __shared__ float slut[CODES];
        if (threadIdx.x < CODES) slut[threadIdx.x] = lut[threadIdx.x];
        __syncthreads();
        size_t i = ((size_t)(blockIdx.x - XBLOCKS) * 256 + threadIdx.x) * 4;
        int4 v = *reinterpret_cast<const int4*>(idx + i);
        float s = scale[i >> 12];   // K_TOTAL elements per output row
        uint2 o;
        o.x = h2u(__floats2half2_rn(slut[v.x] * s, slut[v.y] * s));
        o.y = h2u(__floats2half2_rn(slut[v.z] * s, slut[v.w] * s));
        *reinterpret_cast<uint2*>(g_W + i) = o;
    }
}

// ---------------------------------------------------------------------------
// Persistent GEMM: 148 CTAs; each walks tiles bid, bid+148, ...
// CTA tile = 128(M) x 256(N); BK=128, 2 smem stages; 8 warps (2M x 4N),
// warp tile 64x64; fragment double-buffer pipelined across kit AND tile
// boundaries. Wait+barrier at ks6; ks7 is barrier-free.
// ---------------------------------------------------------------------------
__global__ void __launch_bounds__(256, 1) gemm_kernel(const __half* __restrict__ X,
                                                      const __half* __restrict__ W,
                                                      float* __restrict__ out) {
    extern __shared__ __half sm[];
    const uint32_t smem_base = smem_u32(sm);
    const int tid  = threadIdx.x;
    const int lane = tid & 31;
    const int wid  = tid >> 5;
    const int warp_m = wid & 1;    // 64-row band
    const int warp_n = wid >> 1;   // 64-col band (0..3)

    // --- cp.async mapping: chunk q -> row = (tid>>4) + 16q, col = (tid&15)*8
    const int crow = tid >> 4, ccol = tid & 15;
    const size_t   offA  = (size_t)crow * K_TOTAL + ccol * 8;   // same for B
    const uint32_t dA    = (uint32_t)(crow * BKP + ccol * 8) * 2;
    const uint32_t dB    = (uint32_t)(A_STAGE_HALFS + crow * BKP + ccol * 8) * 2;
    const size_t   gstep = (size_t)16 * K_TOTAL;
    const uint32_t dstep = (uint32_t)(16 * BKP) * 2;

    // --- ldmatrix per-thread byte offsets within a stage ---
    const uint32_t a_off0 = (uint32_t)((warp_m * 64 + (lane & 15)) * BKP
                                       + (lane >> 4) * 8) * 2;
    const uint32_t b_off0 = (uint32_t)(A_STAGE_HALFS * 2)
        + (uint32_t)((warp_n * 64 + (lane & 7) + ((lane >> 4) & 1) * 8) * BKP
                     + ((lane >> 3) & 1) * 8) * 2;

    float acc[4][8][4];
    uint32_t a[2][4][4], b[2][8][2];

    #define LOAD_FRAGS(bf, sb, colk) do {                                      \
        const uint32_t _aB = (sb) + a_off0 + (uint32_t)((colk) * 16 * 2);      \
        const uint32_t _bB = (sb) + b_off0 + (uint32_t)((colk) * 16 * 2);      \
        _Pragma("unroll")                                                      \
        for (int _t = 0; _t < 4; _t++)                                         \
            LDSM4(a[bf][_t][0], a[bf][_t][1], a[bf][_t][2], a[bf][_t][3],      \
                  _aB + (uint32_t)(_t * 16 * BKP) * 2);                        \
        _Pragma("unroll")                                                      \
        for (int _jj = 0; _jj < 4; _jj++)                                      \
            LDSM4(b[bf][_jj * 2][0], b[bf][_jj * 2][1],                        \
                  b[bf][_jj * 2 + 1][0], b[bf][_jj * 2 + 1][1],                \
                  _bB + (uint32_t)(_jj * 16 * BKP) * 2);                       \
    } while (0)

    int tile = blockIdx.x;

    // --- prologue: fill stage 0 of the first tile ---
    {
        const int m_base = (tile >> 4) * BM;   // 16 n-tiles, n fastest
        const int n_base = (tile & 15) * BN;
        const __half* pA = X + (size_t)m_base * K_TOTAL + offA;
        const __half* pB = W + (size_t)n_base * K_TOTAL + offA;
        #pragma unroll
        for (int q = 0; q < 8; q++)  CP_ASYNC16(smem_base + dA + q * dstep, pA + q * gstep);
        #pragma unroll
        for (int q = 0; q < 16; q++) CP_ASYNC16(smem_base + dB + q * dstep, pB + q * gstep);
        CP_COMMIT();
    }
    CP_WAIT(0);
    __syncthreads();
    LOAD_FRAGS(0, smem_base, 0);

    // --- persistent tile loop ---
    while (true) {
        const int m_base = (tile >> 4) * BM;
        const int n_base = (tile & 15) * BN;
        const __half* gA = X + (size_t)m_base * K_TOTAL + offA;
        const __half* gB = W + (size_t)n_base * K_TOTAL + offA;

        const int  next_tile = tile + GRID;
        const bool has_next_tile = next_tile < NTILES;
        const __half* nA = has_next_tile
            ? X + (size_t)((next_tile >> 4) * BM) * K_TOTAL + offA : gA;
        const __half* nB = has_next_tile
            ? W + (size_t)((next_tile & 15) * BN) * K_TOTAL + offA : gB;

        #pragma unroll
        for (int t = 0; t < 4; t++)
            #pragma unroll
            for (int j = 0; j < 8; j++)
                #pragma unroll
                for (int e = 0; e < 4; e++) acc[t][j][e] = 0.f;

        for (int kit = 0; kit < NITER; kit++) {
            const uint32_t sb  = smem_base + (uint32_t)((kit & 1) * STAGE_HALFS) * 2;
            const uint32_t sb2 = smem_base + (uint32_t)(((kit + 1) & 1) * STAGE_HALFS) * 2;
            const bool last_kit = (kit == NITER - 1);
            const __half* pA = last_kit ? nA : gA + (size_t)(kit + 1) * BK;
            const __half* pB = last_kit ? nB : gB + (size_t)(kit + 1) * BK;
            const bool do_pref = !last_kit || has_next_tile;

            #pragma unroll
            for (int ks = 0; ks < KS_PER_KIT; ks++) {
                const int cur = ks & 1, nxt = cur ^ 1;

                if (ks < 4 && do_pref) {   // 6 cp.async issues per step
                    #pragma unroll
                    for (int u = 0; u < 2; u++) {
                        int q = 2 * ks + u;
                        CP_ASYNC16(sb2 + dA + q * dstep, pA + q * gstep);
                    }
                    #pragma unroll
                    for (int u = 0; u < 4; u++) {
                        int q = 4 * ks + u;
                        CP_ASYNC16(sb2 + dB + q * dstep, pB + q * gstep);
                    }
                    if (ks == 3) CP_COMMIT();
                }

                // Decoupled wait: prove stage kit+1 resident at ks6 (3 MMA
                // bursts after the ks3 commit); ks7's cross-kit LDSM then
                // has no wait/barrier in front of it.
                if (ks == 6 && do_pref) {
                    CP_WAIT(0);
                    __syncthreads();
                }

                if (ks < KS_PER_KIT - 1) {
                    LOAD_FRAGS(nxt, sb, ks + 1);
                } else if (do_pref) {
                    LOAD_FRAGS(nxt, sb2, 0);
                }

                #pragma unroll
                for (int t = 0; t < 4; t++)
                    #pragma unroll
                    for (int j = 0; j < 8; j++)
                        mma16816(acc[t][j], a[cur][t], b[cur][j]);
            }
        }

        // --- epilogue (overlaps next tile's in-flight stage-0 copies) ---
        #pragma unroll
        for (int t = 0; t < 4; t++) {
            int row = m_base + warp_m * 64 + t * 16 + (lane >> 2);
            #pragma unroll
            for (int j = 0; j < 8; j++) {
                int col = n_base + warp_n * 64 + j * 8 + (lane & 3) * 2;
                float* p0 = out + (size_t)row * N_TOTAL + col;
                float* p1 = out + (size_t)(row + 8) * N_TOTAL + col;
                STG_CS_F2(p0, acc[t][j][0], acc[t][j][1]);
                STG_CS_F2(p1, acc[t][j][2], acc[t][j][3]);
            }
        }

        if (!has_next_tile) break;
        tile = next_tile;
    }
    #undef LOAD_FRAGS
}

// ---------------------------------------------------------------------------
// Host launcher
// ---------------------------------------------------------------------------
extern "C" void kernel_launch(void* const* d_in, const int* in_sizes, int n_in,
                              void* d_out, int out_size) {
    (void)in_sizes; (void)n_in; (void)out_size;
    const float* x     = (const float*)d_in[0];
    const float* scale = (const float*)d_in[1];
    const float* lut   = (const float*)d_in[2];
    const int*   idx   = (const int*)d_in[3];
    float* out = (float*)d_out;

    void *pX = nullptr, *pW = nullptr;
    cudaGetSymbolAddress(&pX, g_X);
    cudaGetSymbolAddress(&pW, g_W);

    cudaFuncSetAttribute(gemm_kernel, cudaFuncAttributeMaxDynamicSharedMemorySize,
                         SMEM_BYTES);

    convert_kernel<<<XBLOCKS + WBLOCKS, 256>>>(x, idx, scale, lut);

    gemm_kernel<<<GRID, 256, SMEM_BYTES>>>((const __half*)pX, (const __half*)pW, out);
}